// round 1
// baseline (speedup 1.0000x reference)
#include <cuda_runtime.h>
#include <math.h>

// Shapes (hardcoded for this problem instance)
#define BB   2
#define HH   16
#define SS   2048
#define DD   128
#define MM   4096          // memories per head
#define QQ   4096          // B*S queries per head

#define TQ   128           // query tile per CTA
#define TM   128           // memory tile per iteration
#define NTHREADS 256

// Scratch: normalized queries and keys (32 MB each)
__device__ float g_qn[HH * QQ * DD];
__device__ float g_kn[HH * MM * DD];

// ---------------------------------------------------------------------------
// Normalization kernels: one warp per 128-float row
// ---------------------------------------------------------------------------
__global__ void norm_k_kernel(const float* __restrict__ km) {
    int wid  = (blockIdx.x * blockDim.x + threadIdx.x) >> 5;
    int lane = threadIdx.x & 31;
    if (wid >= HH * MM) return;
    float4 v = __ldg(((const float4*)(km + (size_t)wid * DD)) + lane);
    float ss = v.x * v.x + v.y * v.y + v.z * v.z + v.w * v.w;
    #pragma unroll
    for (int o = 16; o > 0; o >>= 1) ss += __shfl_xor_sync(0xffffffffu, ss, o);
    float inv = 1.0f / fmaxf(sqrtf(ss), 1e-11f);
    float4 r = make_float4(v.x * inv, v.y * inv, v.z * inv, v.w * inv);
    ((float4*)(g_kn + (size_t)wid * DD))[lane] = r;
}

__global__ void norm_q_kernel(const float* __restrict__ query) {
    int wid  = (blockIdx.x * blockDim.x + threadIdx.x) >> 5;
    int lane = threadIdx.x & 31;
    if (wid >= HH * QQ) return;
    int h = wid >> 12;          // / 4096
    int q = wid & (QQ - 1);
    int b = q >> 11;            // / 2048
    int s = q & (SS - 1);
    size_t src = ((size_t)((b * HH + h) * SS + s)) * DD;
    float4 v = __ldg(((const float4*)(query + src)) + lane);
    float ss = v.x * v.x + v.y * v.y + v.z * v.z + v.w * v.w;
    #pragma unroll
    for (int o = 16; o > 0; o >>= 1) ss += __shfl_xor_sync(0xffffffffu, ss, o);
    float inv = 1.0f / fmaxf(sqrtf(ss), 1e-11f);
    float4 r = make_float4(v.x * inv, v.y * inv, v.z * inv, v.w * inv);
    ((float4*)(g_qn + (size_t)wid * DD))[lane] = r;
}

// ---------------------------------------------------------------------------
// Load a 128x128 fp32 tile (row-major [row][d]) into SMEM transposed [d][row]
// with XOR group-swizzle: element (row, d) -> dst[d*128 + ((row>>2)^((d>>2)&7))*4 + (row&3)]
// Keeps compute-side float4 loads aligned; store conflicts ~4-way.
// ---------------------------------------------------------------------------
__device__ __forceinline__ void load_tile_T(const float* __restrict__ src,
                                            float* __restrict__ dst, int tid) {
    #pragma unroll
    for (int i = 0; i < 16; ++i) {
        int f   = i * 256 + tid;        // float4 index 0..4095
        int row = f >> 5;               // 0..127
        int d0  = (f & 31) << 2;        // 0..124
        float4 v = __ldg((const float4*)(src + (size_t)row * DD + d0));
        float vv[4] = {v.x, v.y, v.z, v.w};
        int cg = row >> 2;
        int rl = row & 3;
        #pragma unroll
        for (int j = 0; j < 4; ++j) {
            int d = d0 + j;
            dst[d * 128 + (((cg) ^ ((d >> 2) & 7)) << 2) + rl] = vv[j];
        }
    }
}

// Register-resident top-16 insert (all indices static after unroll -> no spill)
__device__ __forceinline__ void insert16(float v, int idx,
                                         float tv[16], int ti[16],
                                         float& tmin, int& pmin) {
    #pragma unroll
    for (int j = 0; j < 16; ++j) {
        if (j == pmin) { tv[j] = v; ti[j] = idx; }
    }
    tmin = tv[0]; pmin = 0;
    #pragma unroll
    for (int j = 1; j < 16; ++j) {
        if (tv[j] < tmin) { tmin = tv[j]; pmin = j; }
    }
}

// ---------------------------------------------------------------------------
// Fused kernel: per (head, 128-query tile):
//   loop over M in 128-chunks: SGEMM 128x128x128 -> SMEM sims -> top-16 update
//   then merge halves, gather values, weighted sum, gated blend, write output
// ---------------------------------------------------------------------------
__global__ void __launch_bounds__(NTHREADS, 1)
fused_knn_kernel(const float* __restrict__ vmem,
                 const float* __restrict__ outputs,
                 const float* __restrict__ gate,
                 float* __restrict__ out) {
    extern __shared__ float sm[];
    float* Qs = sm;                 // 16384 floats: Q tile [d][q] swizzled
    float* Ks = sm + 16384;         // 16384 floats: K tile [d][m] swizzled
    float* Ss = sm + 32768;         // 128*129 floats: sims [q][m] padded

    const int h     = blockIdx.y;
    const int qbase = blockIdx.x * TQ;
    const int tid   = threadIdx.x;
    const int ty    = tid >> 4;     // 0..15 (query sub-rows)
    const int tx    = tid & 15;     // 0..15 (memory sub-cols)
    const int srow  = tid & 127;    // selection row
    const int shalf = tid >> 7;     // selection half (0/1)

    // Load and keep the Q tile resident
    load_tile_T(g_qn + ((size_t)(h * QQ + qbase)) * DD, Qs, tid);

    // top-16 state (registers)
    float tv[16]; int ti[16];
    #pragma unroll
    for (int j = 0; j < 16; ++j) { tv[j] = -1e30f; ti[j] = 0; }
    float tmin = -1e30f; int pmin = 0;

    const float* kh = g_kn + (size_t)h * MM * DD;

    for (int mt = 0; mt < MM; mt += TM) {
        __syncthreads();  // prev selection done with Ss; prev GEMM done with Ks; Qs ready (1st)
        load_tile_T(kh + (size_t)mt * DD, Ks, tid);
        __syncthreads();

        float acc[8][8];
        #pragma unroll
        for (int i = 0; i < 8; ++i)
            #pragma unroll
            for (int j = 0; j < 8; ++j) acc[i][j] = 0.0f;

        #pragma unroll 4
        for (int kk = 0; kk < 128; ++kk) {
            int s = (kk >> 2) & 7;
            const float4 a0 = *(const float4*)&Qs[kk * 128 + (((ty * 2)     ^ s) << 2)];
            const float4 a1 = *(const float4*)&Qs[kk * 128 + (((ty * 2 + 1) ^ s) << 2)];
            const float4 b0 = *(const float4*)&Ks[kk * 128 + (((tx * 2)     ^ s) << 2)];
            const float4 b1 = *(const float4*)&Ks[kk * 128 + (((tx * 2 + 1) ^ s) << 2)];
            float a[8] = {a0.x, a0.y, a0.z, a0.w, a1.x, a1.y, a1.z, a1.w};
            float b[8] = {b0.x, b0.y, b0.z, b0.w, b1.x, b1.y, b1.z, b1.w};
            #pragma unroll
            for (int i = 0; i < 8; ++i)
                #pragma unroll
                for (int j = 0; j < 8; ++j) acc[i][j] += a[i] * b[j];
        }

        // stage sims to shared (padded stride 129 -> conflict-free column scans)
        #pragma unroll
        for (int i = 0; i < 8; ++i)
            #pragma unroll
            for (int j = 0; j < 8; ++j)
                Ss[(ty * 8 + i) * 129 + tx * 8 + j] = acc[i][j];
        __syncthreads();

        // selection: thread (srow, shalf) scans 64 candidates
        const float* sp = Ss + srow * 129 + shalf * 64;
        const int base = mt + shalf * 64;
        #pragma unroll 4
        for (int c = 0; c < 64; ++c) {
            float v = sp[c];
            if (v > tmin) insert16(v, base + c, tv, ti, tmin, pmin);
        }
    }

    // ---- merge the two halves per row ----
    __syncthreads();
    float* MV = Ks;                       // 128*32 floats
    int*   MI = (int*)(Ks + 4096);        // 128*32 ints
    {
        int mb = srow * 32 + shalf * 16;
        #pragma unroll
        for (int j = 0; j < 16; ++j) { MV[mb + j] = tv[j]; MI[mb + j] = ti[j]; }
    }
    __syncthreads();

    float* FV = Qs;                       // 128*16 floats
    int*   FI = (int*)(Qs + 2048);        // 128*16 ints
    if (tid < 128) {
        #pragma unroll
        for (int j = 0; j < 16; ++j) { tv[j] = -1e30f; ti[j] = 0; }
        tmin = -1e30f; pmin = 0;
        #pragma unroll 2
        for (int c = 0; c < 32; ++c) {
            float v = MV[tid * 32 + c];
            if (v > tmin) insert16(v, MI[tid * 32 + c], tv, ti, tmin, pmin);
        }
        #pragma unroll
        for (int j = 0; j < 16; ++j) { FV[tid * 16 + j] = tv[j]; FI[tid * 16 + j] = ti[j]; }
    }
    __syncthreads();

    // ---- weighted value gather + gated blend ----
    const int row = tid >> 1;             // 0..127
    const int dh  = (tid & 1) << 6;       // 0 or 64
    float accd[64];
    #pragma unroll
    for (int t = 0; t < 64; ++t) accd[t] = 0.0f;

    const float* vh = vmem + (size_t)h * MM * DD;
    for (int j = 0; j < 16; ++j) {
        float sc = FV[row * 16 + j];
        int   ix = FI[row * 16 + j];
        const float4* vp = (const float4*)(vh + (size_t)ix * DD + dh);
        #pragma unroll
        for (int t = 0; t < 16; ++t) {
            float4 w = __ldg(vp + t);
            accd[4 * t + 0] += sc * w.x;
            accd[4 * t + 1] += sc * w.y;
            accd[4 * t + 2] += sc * w.z;
            accd[4 * t + 3] += sc * w.w;
        }
    }

    // Output flat index == wm flat index (raw reshape); gate head from out layout
    size_t l = ((size_t)(h * QQ + qbase + row)) * DD + dh;
    int hout = (int)((l >> 18) & (HH - 1));     // S*D = 2^18
    float gg = 1.0f / (1.0f + expf(-__ldg(gate + hout)));
    float og = 1.0f - gg;

    const float4* op = (const float4*)(outputs + l);
    float4*       wp = (float4*)(out + l);
    #pragma unroll
    for (int t = 0; t < 16; ++t) {
        float4 o = __ldg(op + t);
        float4 r;
        r.x = gg * accd[4 * t + 0] + og * o.x;
        r.y = gg * accd[4 * t + 1] + og * o.y;
        r.z = gg * accd[4 * t + 2] + og * o.z;
        r.w = gg * accd[4 * t + 3] + og * o.w;
        wp[t] = r;
    }
}

// ---------------------------------------------------------------------------
extern "C" void kernel_launch(void* const* d_in, const int* in_sizes, int n_in,
                              void* d_out, int out_size) {
    // metadata order: inputs, query, key, value, outputs, gate, key_memories, value_memories
    const float* query   = (const float*)d_in[1];
    const float* outputs = (const float*)d_in[4];
    const float* gate    = (const float*)d_in[5];
    const float* kmem    = (const float*)d_in[6];
    const float* vmem    = (const float*)d_in[7];
    float* out = (float*)d_out;

    const int smem_bytes = (32768 + 128 * 129) * (int)sizeof(float);  // 197120
    cudaFuncSetAttribute(fused_knn_kernel,
                         cudaFuncAttributeMaxDynamicSharedMemorySize, smem_bytes);

    // 65536 rows each, 8 warps per block
    norm_k_kernel<<<(HH * MM) / 8, 256>>>(kmem);
    norm_q_kernel<<<(HH * QQ) / 8, 256>>>(query);

    dim3 grid(QQ / TQ, HH);  // (32, 16)
    fused_knn_kernel<<<grid, NTHREADS, smem_bytes>>>(vmem, outputs, gate, out);
}